// round 7
// baseline (speedup 1.0000x reference)
#include <cuda_runtime.h>
#include <cuda_bf16.h>
#include <math.h>

// Problem constants
#define EG 1024      // embed dim
#define MG 2048      // B*S rows
#define SG 1024      // seq len
#define HG 16        // heads
#define DH 64        // head dim

// ---------------- scratch (device globals: no runtime allocation allowed) ----
__device__ float g_qa[MG * EG];
__device__ float g_qb[MG * EG];
__device__ float g_ka[MG * EG];
__device__ float g_kb[MG * EG];
__device__ float g_va[MG * EG];
__device__ float g_vb[MG * EG];
__device__ float g_oa[MG * EG];
__device__ float g_ob[MG * EG];

// pre-split bf16 hi/lo buffers
// weights: 0 q_wa, 1 q_wb, 2 k_wa, 3 k_wb, 4 v_wa, 5 v_wb, 6 o_wa, 7 o_wb
__device__ __nv_bfloat16 g_wH[8][EG * EG];
__device__ __nv_bfloat16 g_wL[8][EG * EG];
// activations: 0 x_q_a, 1 x_q_b, 2 x_kv_a, 3 x_kv_b, 4 oa, 5 ob
__device__ __nv_bfloat16 g_xH[6][MG * EG];
__device__ __nv_bfloat16 g_xL[6][MG * EG];

// ---------------------------------------------------------------------------
// helpers
// ---------------------------------------------------------------------------
__device__ __forceinline__ void mma_bf16(float* c, const unsigned* a, const unsigned* b)
{
    asm volatile(
        "mma.sync.aligned.m16n8k16.row.col.f32.bf16.bf16.f32 "
        "{%0,%1,%2,%3}, {%4,%5,%6,%7}, {%8,%9}, {%0,%1,%2,%3};"
        : "+f"(c[0]), "+f"(c[1]), "+f"(c[2]), "+f"(c[3])
        : "r"(a[0]), "r"(a[1]), "r"(a[2]), "r"(a[3]),
          "r"(b[0]), "r"(b[1]));
}

__device__ __forceinline__ unsigned pack_hi2(float x, float y)
{
    __nv_bfloat162 h(__float2bfloat16(x), __float2bfloat16(y));
    return *reinterpret_cast<unsigned*>(&h);
}
__device__ __forceinline__ unsigned pack_lo2(float x, float y)
{
    float hx = __bfloat162float(__float2bfloat16(x));
    float hy = __bfloat162float(__float2bfloat16(y));
    __nv_bfloat162 l(__float2bfloat16(x - hx), __float2bfloat16(y - hy));
    return *reinterpret_cast<unsigned*>(&l);
}

__device__ __forceinline__ void cp_async16(unsigned daddr, const void* src)
{
    asm volatile("cp.async.cg.shared.global [%0], [%1], 16;" :: "r"(daddr), "l"(src));
}
__device__ __forceinline__ void cp_commit()
{
    asm volatile("cp.async.commit_group;");
}
template<int N>
__device__ __forceinline__ void cp_wait()
{
    asm volatile("cp.async.wait_group %0;" :: "n"(N));
}

// smem tile strides (bf16 halfword units). BK=32 + pad 8 -> conflict-free frags.
#define TSTR 40
#define TILE_HF (64 * TSTR)

// split fp32 -> bf16 hi/lo, write pairs into smem tiles (used in attention)
__device__ __forceinline__ void split_store4(
    __nv_bfloat16* shi, __nv_bfloat16* slo, int idx, float4 v)
{
    __nv_bfloat16 hx = __float2bfloat16(v.x);
    __nv_bfloat16 hy = __float2bfloat16(v.y);
    __nv_bfloat16 hz = __float2bfloat16(v.z);
    __nv_bfloat16 hw = __float2bfloat16(v.w);
    __nv_bfloat16 lx = __float2bfloat16(v.x - __bfloat162float(hx));
    __nv_bfloat16 ly = __float2bfloat16(v.y - __bfloat162float(hy));
    __nv_bfloat16 lz = __float2bfloat16(v.z - __bfloat162float(hz));
    __nv_bfloat16 lw = __float2bfloat16(v.w - __bfloat162float(hw));
    *reinterpret_cast<__nv_bfloat162*>(&shi[idx])     = __nv_bfloat162(hx, hy);
    *reinterpret_cast<__nv_bfloat162*>(&shi[idx + 2]) = __nv_bfloat162(hz, hw);
    *reinterpret_cast<__nv_bfloat162*>(&slo[idx])     = __nv_bfloat162(lx, ly);
    *reinterpret_cast<__nv_bfloat162*>(&slo[idx + 2]) = __nv_bfloat162(lz, lw);
}

// load A fragment (m16 x k16) from row-major [64][TSTR] bf16 tile
__device__ __forceinline__ void load_afrag(
    unsigned* a, const __nv_bfloat16* s, int mbase, int sk, int g, int t)
{
    const int r0 = (mbase + g) * TSTR + sk + 2 * t;
    const int r1 = (mbase + g + 8) * TSTR + sk + 2 * t;
    a[0] = *reinterpret_cast<const unsigned*>(&s[r0]);
    a[1] = *reinterpret_cast<const unsigned*>(&s[r1]);
    a[2] = *reinterpret_cast<const unsigned*>(&s[r0 + 8]);
    a[3] = *reinterpret_cast<const unsigned*>(&s[r1 + 8]);
}

// load B fragment (k16 x n8, col layout == W[n][k] row-major) from [n][stride]
template<int STRIDE>
__device__ __forceinline__ void load_bfragS(
    unsigned* b, const __nv_bfloat16* s, int nbase, int sk, int g, int t)
{
    const int r = (nbase + g) * STRIDE + sk + 2 * t;
    b[0] = *reinterpret_cast<const unsigned*>(&s[r]);
    b[1] = *reinterpret_cast<const unsigned*>(&s[r + 8]);
}

// ---------------------------------------------------------------------------
// Batched fp32 -> bf16 hi/lo split. blockIdx.y selects the tensor.
// ---------------------------------------------------------------------------
struct SplitBatch {
    const float* src[8];
    __nv_bfloat16* hi[8];
    __nv_bfloat16* lo[8];
};

__global__ __launch_bounds__(256) void split_kernel(SplitBatch sb, int nvec)
{
    const int t = blockIdx.x * 256 + threadIdx.x;
    if (t >= nvec) return;
    const int w = blockIdx.y;
    const float4 v = reinterpret_cast<const float4*>(sb.src[w])[t];

    unsigned h0 = pack_hi2(v.x, v.y);
    unsigned h1 = pack_hi2(v.z, v.w);
    unsigned l0 = pack_lo2(v.x, v.y);
    unsigned l1 = pack_lo2(v.z, v.w);

    reinterpret_cast<uint2*>(sb.hi[w])[t] = make_uint2(h0, h1);
    reinterpret_cast<uint2*>(sb.lo[w])[t] = make_uint2(l0, l1);
}

// ---------------------------------------------------------------------------
// Fused quaternion-complex dense on tensor cores, pre-split bf16 inputs,
// cp.async double-buffered mainloop.
//   outA = Xa.Wa^T + j2 * Xb.Wb^T + ba ;  outB = Xa.Wb^T + Xb.Wa^T + bb
// 64x64 CTA tile, BK=32, 256 threads = 8 warps (4x2), warp tile 16x32.
// smem: 2 stages x 8 tiles (XaH,XaL,XbH,XbL,WaH,WaL,WbH,WbL) x [64][TSTR].
// Loader: tid<128 -> hi tiles, tid>=128 -> lo tiles. Per tile, thread tt
// covers chunks tt and tt+128 of 256 16B chunks:
//   row = chunk>>2 (0..63), col = (chunk&3)*8 elements (16B).
// ---------------------------------------------------------------------------
__global__ __launch_bounds__(256) void qc_gemm_bf16_kernel(
    const __nv_bfloat16* __restrict__ xaH, const __nv_bfloat16* __restrict__ xaL,
    const __nv_bfloat16* __restrict__ xbH, const __nv_bfloat16* __restrict__ xbL,
    const __nv_bfloat16* __restrict__ waH, const __nv_bfloat16* __restrict__ waL,
    const __nv_bfloat16* __restrict__ wbH, const __nv_bfloat16* __restrict__ wbL,
    const float* __restrict__ ba, const float* __restrict__ bb,
    const float* __restrict__ theta_ptr,
    float* __restrict__ outA, float* __restrict__ outB)
{
    extern __shared__ __nv_bfloat16 sbuf[];

    const int tid = threadIdx.x;
    const int lane = tid & 31;
    const int wid = tid >> 5;
    const int warp_m = wid >> 1;
    const int warp_n = wid & 1;
    const int g = lane >> 2;
    const int t = lane & 3;

    const int m0 = blockIdx.y * 64;
    const int n0 = blockIdx.x * 64;

    const float j2 = sinf(2.0f * theta_ptr[0]) - 1.0f;

    // loader mapping (FIXED): full 4096B tile coverage, 16B-aligned chunks
    const int losel = tid >> 7;           // 0 hi, 1 lo
    const int tt    = tid & 127;
    const int lr0   = tt >> 2;            // rows 0..31 (chunk j=0)
    const int lc0   = (tt & 3) << 3;      // cols 0,8,16,24 (elements)
    // chunk j=1: row lr0+32, same col

    const __nv_bfloat16* sxa = (losel ? xaL : xaH) + (size_t)(m0 + lr0) * EG + lc0;
    const __nv_bfloat16* sxb = (losel ? xbL : xbH) + (size_t)(m0 + lr0) * EG + lc0;
    const __nv_bfloat16* swa = (losel ? waL : waH) + (size_t)(n0 + lr0) * EG + lc0;
    const __nv_bfloat16* swb = (losel ? wbL : wbH) + (size_t)(n0 + lr0) * EG + lc0;
    const size_t GROW = (size_t)32 * EG;  // +32 rows in gmem

    const int doff0 = lr0 * TSTR + lc0;
    const int doff1 = doff0 + 32 * TSTR;
    unsigned dxa[2][2], dxb[2][2], dwa[2][2], dwb[2][2];
    #pragma unroll
    for (int st = 0; st < 2; st++) {
        __nv_bfloat16* base = sbuf + st * 8 * TILE_HF;
        __nv_bfloat16* bxa = base + (0 + losel) * TILE_HF;
        __nv_bfloat16* bxb = base + (2 + losel) * TILE_HF;
        __nv_bfloat16* bwa = base + (4 + losel) * TILE_HF;
        __nv_bfloat16* bwb = base + (6 + losel) * TILE_HF;
        dxa[st][0] = (unsigned)__cvta_generic_to_shared(bxa + doff0);
        dxa[st][1] = (unsigned)__cvta_generic_to_shared(bxa + doff1);
        dxb[st][0] = (unsigned)__cvta_generic_to_shared(bxb + doff0);
        dxb[st][1] = (unsigned)__cvta_generic_to_shared(bxb + doff1);
        dwa[st][0] = (unsigned)__cvta_generic_to_shared(bwa + doff0);
        dwa[st][1] = (unsigned)__cvta_generic_to_shared(bwa + doff1);
        dwb[st][0] = (unsigned)__cvta_generic_to_shared(bwb + doff0);
        dwb[st][1] = (unsigned)__cvta_generic_to_shared(bwb + doff1);
    }

    float accA1[4][4] = {};
    float accA2[4][4] = {};
    float accB [4][4] = {};

    // prologue: stage 0, k0 = 0
    cp_async16(dxa[0][0], sxa);          cp_async16(dxa[0][1], sxa + GROW);
    cp_async16(dxb[0][0], sxb);          cp_async16(dxb[0][1], sxb + GROW);
    cp_async16(dwa[0][0], swa);          cp_async16(dwa[0][1], swa + GROW);
    cp_async16(dwb[0][0], swb);          cp_async16(dwb[0][1], swb + GROW);
    cp_commit();

    const int NIT = EG / 32;
    for (int it = 0; it < NIT; it++) {
        const int cur = it & 1;
        if (it + 1 < NIT) {
            const int nk = (it + 1) * 32;
            const int ns = 1 - cur;
            cp_async16(dxa[ns][0], sxa + nk);   cp_async16(dxa[ns][1], sxa + nk + GROW);
            cp_async16(dxb[ns][0], sxb + nk);   cp_async16(dxb[ns][1], sxb + nk + GROW);
            cp_async16(dwa[ns][0], swa + nk);   cp_async16(dwa[ns][1], swa + nk + GROW);
            cp_async16(dwb[ns][0], swb + nk);   cp_async16(dwb[ns][1], swb + nk + GROW);
            cp_commit();
            cp_wait<1>();
        } else {
            cp_wait<0>();
        }
        __syncthreads();

        const __nv_bfloat16* cb = sbuf + cur * 8 * TILE_HF;
        const __nv_bfloat16* sXaH = cb + 0 * TILE_HF;
        const __nv_bfloat16* sXaL = cb + 1 * TILE_HF;
        const __nv_bfloat16* sXbH = cb + 2 * TILE_HF;
        const __nv_bfloat16* sXbL = cb + 3 * TILE_HF;
        const __nv_bfloat16* sWaH = cb + 4 * TILE_HF;
        const __nv_bfloat16* sWaL = cb + 5 * TILE_HF;
        const __nv_bfloat16* sWbH = cb + 6 * TILE_HF;
        const __nv_bfloat16* sWbL = cb + 7 * TILE_HF;

        #pragma unroll
        for (int ks = 0; ks < 2; ks++) {
            const int sk = ks * 16;
            unsigned aXaH[4], aXaL[4], aXbH[4], aXbL[4];
            load_afrag(aXaH, sXaH, warp_m * 16, sk, g, t);
            load_afrag(aXaL, sXaL, warp_m * 16, sk, g, t);
            load_afrag(aXbH, sXbH, warp_m * 16, sk, g, t);
            load_afrag(aXbL, sXbL, warp_m * 16, sk, g, t);

            #pragma unroll
            for (int f = 0; f < 4; f++) {
                const int nbase = warp_n * 32 + f * 8;
                unsigned bWaH[2], bWaL[2], bWbH[2], bWbL[2];
                load_bfragS<TSTR>(bWaH, sWaH, nbase, sk, g, t);
                load_bfragS<TSTR>(bWaL, sWaL, nbase, sk, g, t);
                load_bfragS<TSTR>(bWbH, sWbH, nbase, sk, g, t);
                load_bfragS<TSTR>(bWbL, sWbL, nbase, sk, g, t);

                mma_bf16(accA1[f], aXaH, bWaH);
                mma_bf16(accA1[f], aXaH, bWaL);
                mma_bf16(accA1[f], aXaL, bWaH);
                mma_bf16(accA2[f], aXbH, bWbH);
                mma_bf16(accA2[f], aXbH, bWbL);
                mma_bf16(accA2[f], aXbL, bWbH);
                mma_bf16(accB[f], aXaH, bWbH);
                mma_bf16(accB[f], aXaH, bWbL);
                mma_bf16(accB[f], aXaL, bWbH);
                mma_bf16(accB[f], aXbH, bWaH);
                mma_bf16(accB[f], aXbH, bWaL);
                mma_bf16(accB[f], aXbL, bWaH);
            }
        }
        __syncthreads();   // compute done before this stage is refilled
    }

    #pragma unroll
    for (int f = 0; f < 4; f++) {
        const int n = n0 + warp_n * 32 + f * 8 + 2 * t;
        const int r0 = m0 + warp_m * 16 + g;
        const int r1 = r0 + 8;
        const float ba0 = ba[n], ba1 = ba[n + 1];
        const float bb0 = bb[n], bb1 = bb[n + 1];

        float2 oa0 = { accA1[f][0] + j2 * accA2[f][0] + ba0,
                       accA1[f][1] + j2 * accA2[f][1] + ba1 };
        float2 oa1 = { accA1[f][2] + j2 * accA2[f][2] + ba0,
                       accA1[f][3] + j2 * accA2[f][3] + ba1 };
        float2 ob0 = { accB[f][0] + bb0, accB[f][1] + bb1 };
        float2 ob1 = { accB[f][2] + bb0, accB[f][3] + bb1 };

        *(float2*)&outA[r0 * EG + n] = oa0;
        *(float2*)&outA[r1 * EG + n] = oa1;
        *(float2*)&outB[r0 * EG + n] = ob0;
        *(float2*)&outB[r1 * EG + n] = ob1;
    }
}

// ---------------------------------------------------------------------------
// RoPE applied in place to g_qa, g_qb, g_ka, g_kb (fp32 throughout).
// ---------------------------------------------------------------------------
__global__ __launch_bounds__(256) void rope_kernel()
{
    const int PAIRS = MG * (EG / 2);
    int tt = blockIdx.x * blockDim.x + threadIdx.x;
    if (tt >= 4 * PAIRS) return;

    const int w = tt / PAIRS;
    const int p = tt % PAIRS;
    float* X = (w == 0) ? g_qa : (w == 1) ? g_qb : (w == 2) ? g_ka : g_kb;

    const int row = p >> 9;
    const int pp  = p & 511;
    const int h   = pp >> 5;
    const int i   = pp & 31;
    const int s   = row & (SG - 1);

    const float freq = exp2f(-(float)i * (13.287712379549449f / 32.0f));
    float sn, cs;
    sincosf((float)s * freq, &sn, &cs);

    const int base = row * EG + h * DH + i;
    const float x1 = X[base];
    const float x2 = X[base + 32];
    X[base]      = x1 * cs - x2 * sn;
    X[base + 32] = x2 * cs + x1 * sn;
}

// ---------------------------------------------------------------------------
// Tensor-core flash attention with complex-magnitude scores, bf16 hi/lo split.
// (unchanged from R4 -- validated at rel_err 3.7e-5)
// ---------------------------------------------------------------------------
#define KSTR 72
#define VSTR 40

__global__ __launch_bounds__(256) void attn_mma_kernel(const float* __restrict__ thetas_head)
{
    __shared__ __nv_bfloat16 sKaH[32 * KSTR], sKaL[32 * KSTR];
    __shared__ __nv_bfloat16 sKbH[32 * KSTR], sKbL[32 * KSTR];
    __shared__ __nv_bfloat16 sKjH[32 * KSTR], sKjL[32 * KSTR];
    __shared__ __nv_bfloat16 sVaH[64 * VSTR], sVaL[64 * VSTR];
    __shared__ __nv_bfloat16 sVbH[64 * VSTR], sVbL[64 * VSTR];

    const int b   = blockIdx.z;
    const int h   = blockIdx.y;
    const int r0  = blockIdx.x * 128;
    const int tid = threadIdx.x;
    const int lane = tid & 31;
    const int wid  = tid >> 5;
    const int g = lane >> 2;
    const int t = lane & 3;

    const float j2h = sinf(2.0f * thetas_head[h]) - 1.0f;

    unsigned qaH[4][4], qaL[4][4], qbH[4][4], qbL[4][4];
    {
        const int row0 = r0 + wid * 16 + g;
        const int base0 = (b * SG + row0) * EG + h * DH;
        const int base1 = base0 + 8 * EG;
        #pragma unroll
        for (int ks = 0; ks < 4; ks++) {
            const int col = ks * 16 + 2 * t;
            float2 a0 = *(const float2*)&g_qa[base0 + col];
            float2 a1 = *(const float2*)&g_qa[base1 + col];
            float2 a2 = *(const float2*)&g_qa[base0 + col + 8];
            float2 a3 = *(const float2*)&g_qa[base1 + col + 8];
            qaH[ks][0] = pack_hi2(a0.x, a0.y); qaL[ks][0] = pack_lo2(a0.x, a0.y);
            qaH[ks][1] = pack_hi2(a1.x, a1.y); qaL[ks][1] = pack_lo2(a1.x, a1.y);
            qaH[ks][2] = pack_hi2(a2.x, a2.y); qaL[ks][2] = pack_lo2(a2.x, a2.y);
            qaH[ks][3] = pack_hi2(a3.x, a3.y); qaL[ks][3] = pack_lo2(a3.x, a3.y);
            float2 b0 = *(const float2*)&g_qb[base0 + col];
            float2 b1 = *(const float2*)&g_qb[base1 + col];
            float2 b2 = *(const float2*)&g_qb[base0 + col + 8];
            float2 b3 = *(const float2*)&g_qb[base1 + col + 8];
            qbH[ks][0] = pack_hi2(b0.x, b0.y); qbL[ks][0] = pack_lo2(b0.x, b0.y);
            qbH[ks][1] = pack_hi2(b1.x, b1.y); qbL[ks][1] = pack_lo2(b1.x, b1.y);
            qbH[ks][2] = pack_hi2(b2.x, b2.y); qbL[ks][2] = pack_lo2(b2.x, b2.y);
            qbH[ks][3] = pack_hi2(b3.x, b3.y); qbL[ks][3] = pack_lo2(b3.x, b3.y);
        }
    }

    float oa[8][4] = {};
    float ob[8][4] = {};
    float mrow0 = -1e30f, mrow1 = -1e30f;
    float lrow0 = 0.0f,   lrow1 = 0.0f;

    const int ntiles = (r0 >> 5) + 4;
    for (int tile = 0; tile < ntiles; tile++) {
        const int k0 = tile * 32;

        __syncthreads();

        #pragma unroll
        for (int it = 0; it < 2; it++) {
            const int idx = tid + it * 256;
            const int n  = idx >> 4;
            const int d4 = (idx & 15) << 2;
            const int ga = (b * SG + k0 + n) * EG + h * DH + d4;
            float4 vka = *(const float4*)&g_ka[ga];
            float4 vkb = *(const float4*)&g_kb[ga];
            const int si = n * KSTR + d4;
            split_store4(sKaH, sKaL, si, vka);
            split_store4(sKbH, sKbL, si, vkb);
            float4 vkj = { j2h * vkb.x, j2h * vkb.y, j2h * vkb.z, j2h * vkb.w };
            split_store4(sKjH, sKjL, si, vkj);
        }
        #pragma unroll
        for (int it = 0; it < 2; it++) {
            const int idx = tid + it * 256;
            const int n  = idx >> 4;
            const int d4 = (idx & 15) << 2;
            const int ga = (b * SG + k0 + n) * EG + h * DH + d4;
            float4 vva = *(const float4*)&g_va[ga];
            float4 vvb = *(const float4*)&g_vb[ga];
            const float va4[4] = { vva.x, vva.y, vva.z, vva.w };
            const float vb4[4] = { vvb.x, vvb.y, vvb.z, vvb.w };
            #pragma unroll
            for (int j = 0; j < 4; j++) {
                const int si = (d4 + j) * VSTR + n;
                __nv_bfloat16 hv = __float2bfloat16(va4[j]);
                sVaH[si] = hv;
                sVaL[si] = __float2bfloat16(va4[j] - __bfloat162float(hv));
                __nv_bfloat16 hw = __float2bfloat16(vb4[j]);
                sVbH[si] = hw;
                sVbL[si] = __float2bfloat16(vb4[j] - __bfloat162float(hw));
            }
        }
        __syncthreads();

        const int wrow = r0 + wid * 16;
        if (k0 > wrow + 15) continue;

        float sa[4][4] = {};
        float sb[4][4] = {};
        #pragma unroll
        for (int ks = 0; ks < 4; ks++) {
            const int sk = ks * 16;
            #pragma unroll
            for (int nf = 0; nf < 4; nf++) {
                const int nb = nf * 8;
                unsigned kaH[2], kaL[2], kbH[2], kbL[2], kjH[2], kjL[2];
                load_bfragS<KSTR>(kaH, sKaH, nb, sk, g, t);
                load_bfragS<KSTR>(kaL, sKaL, nb, sk, g, t);
                load_bfragS<KSTR>(kbH, sKbH, nb, sk, g, t);
                load_bfragS<KSTR>(kbL, sKbL, nb, sk, g, t);
                load_bfragS<KSTR>(kjH, sKjH, nb, sk, g, t);
                load_bfragS<KSTR>(kjL, sKjL, nb, sk, g, t);

                mma_bf16(sa[nf], qaH[ks], kaH);
                mma_bf16(sa[nf], qaH[ks], kaL);
                mma_bf16(sa[nf], qaL[ks], kaH);
                mma_bf16(sa[nf], qbH[ks], kjH);
                mma_bf16(sa[nf], qbH[ks], kjL);
                mma_bf16(sa[nf], qbL[ks], kjH);
                mma_bf16(sb[nf], qaH[ks], kbH);
                mma_bf16(sb[nf], qaH[ks], kbL);
                mma_bf16(sb[nf], qaL[ks], kbH);
                mma_bf16(sb[nf], qbH[ks], kaH);
                mma_bf16(sb[nf], qbH[ks], kaL);
                mma_bf16(sb[nf], qbL[ks], kaH);
            }
        }

        const bool full = (k0 + 31 <= wrow);
        float mt0 = -1e30f, mt1 = -1e30f;
        #pragma unroll
        for (int nf = 0; nf < 4; nf++) {
            #pragma unroll
            for (int c = 0; c < 4; c++) {
                float v = sqrtf(sa[nf][c] * sa[nf][c] + sb[nf][c] * sb[nf][c] + 1e-8f) * 0.125f;
                if (!full) {
                    const int col = k0 + nf * 8 + 2 * t + (c & 1);
                    const int row = wrow + g + ((c & 2) ? 8 : 0);
                    if (col > row) v = -1e9f;
                }
                sa[nf][c] = v;
                if (c & 2) mt1 = fmaxf(mt1, v); else mt0 = fmaxf(mt0, v);
            }
        }
        mt0 = fmaxf(mt0, __shfl_xor_sync(0xffffffffu, mt0, 1));
        mt0 = fmaxf(mt0, __shfl_xor_sync(0xffffffffu, mt0, 2));
        mt1 = fmaxf(mt1, __shfl_xor_sync(0xffffffffu, mt1, 1));
        mt1 = fmaxf(mt1, __shfl_xor_sync(0xffffffffu, mt1, 2));

        const float mn0 = fmaxf(mrow0, mt0);
        const float mn1 = fmaxf(mrow1, mt1);

        float ps0 = 0.0f, ps1 = 0.0f;
        #pragma unroll
        for (int nf = 0; nf < 4; nf++) {
            #pragma unroll
            for (int c = 0; c < 4; c++) {
                const float p = __expf(sa[nf][c] - ((c & 2) ? mn1 : mn0));
                sa[nf][c] = p;
                if (c & 2) ps1 += p; else ps0 += p;
            }
        }
        ps0 += __shfl_xor_sync(0xffffffffu, ps0, 1);
        ps0 += __shfl_xor_sync(0xffffffffu, ps0, 2);
        ps1 += __shfl_xor_sync(0xffffffffu, ps1, 1);
        ps1 += __shfl_xor_sync(0xffffffffu, ps1, 2);

        const float sc0 = __expf(mrow0 - mn0);
        const float sc1 = __expf(mrow1 - mn1);
        lrow0 = lrow0 * sc0 + ps0;  mrow0 = mn0;
        lrow1 = lrow1 * sc1 + ps1;  mrow1 = mn1;
        #pragma unroll
        for (int nf = 0; nf < 8; nf++) {
            oa[nf][0] *= sc0; oa[nf][1] *= sc0; oa[nf][2] *= sc1; oa[nf][3] *= sc1;
            ob[nf][0] *= sc0; ob[nf][1] *= sc0; ob[nf][2] *= sc1; ob[nf][3] *= sc1;
        }

        unsigned pH[2][4], pL[2][4];
        #pragma unroll
        for (int kc = 0; kc < 2; kc++) {
            const int f = 2 * kc;
            pH[kc][0] = pack_hi2(sa[f][0],     sa[f][1]);
            pL[kc][0] = pack_lo2(sa[f][0],     sa[f][1]);
            pH[kc][1] = pack_hi2(sa[f][2],     sa[f][3]);
            pL[kc][1] = pack_lo2(sa[f][2],     sa[f][3]);
            pH[kc][2] = pack_hi2(sa[f + 1][0], sa[f + 1][1]);
            pL[kc][2] = pack_lo2(sa[f + 1][0], sa[f + 1][1]);
            pH[kc][3] = pack_hi2(sa[f + 1][2], sa[f + 1][3]);
            pL[kc][3] = pack_lo2(sa[f + 1][2], sa[f + 1][3]);
        }

        #pragma unroll
        for (int nf = 0; nf < 8; nf++) {
            const int nb = nf * 8;
            #pragma unroll
            for (int kc = 0; kc < 2; kc++) {
                const int sk = kc * 16;
                unsigned vaH[2], vaL[2], vbH[2], vbL[2];
                load_bfragS<VSTR>(vaH, sVaH, nb, sk, g, t);
                load_bfragS<VSTR>(vaL, sVaL, nb, sk, g, t);
                load_bfragS<VSTR>(vbH, sVbH, nb, sk, g, t);
                load_bfragS<VSTR>(vbL, sVbL, nb, sk, g, t);

                mma_bf16(oa[nf], pH[kc], vaH);
                mma_bf16(oa[nf], pL[kc], vaH);
                mma_bf16(oa[nf], pH[kc], vaL);
                mma_bf16(ob[nf], pH[kc], vbH);
                mma_bf16(ob[nf], pL[kc], vbH);
                mma_bf16(ob[nf], pH[kc], vbL);
            }
        }
    }

    const float inv0 = 1.0f / lrow0;
    const float inv1 = 1.0f / lrow1;
    const int row0 = r0 + wid * 16 + g;
    const int base0 = (b * SG + row0) * EG + h * DH;
    const int base1 = base0 + 8 * EG;
    #pragma unroll
    for (int nf = 0; nf < 8; nf++) {
        const int d = nf * 8 + 2 * t;
        float2 va0 = { oa[nf][0] * inv0, oa[nf][1] * inv0 };
        float2 va1 = { oa[nf][2] * inv1, oa[nf][3] * inv1 };
        float2 vb0 = { ob[nf][0] * inv0, ob[nf][1] * inv0 };
        float2 vb1 = { ob[nf][2] * inv1, ob[nf][3] * inv1 };
        *(float2*)&g_oa[base0 + d] = va0;
        *(float2*)&g_oa[base1 + d] = va1;
        *(float2*)&g_ob[base0 + d] = vb0;
        *(float2*)&g_ob[base1 + d] = vb1;
    }
}

// ---------------------------------------------------------------------------
extern "C" void kernel_launch(void* const* d_in, const int* in_sizes, int n_in,
                              void* d_out, int out_size)
{
    const float* x_q_a  = (const float*)d_in[0];
    const float* x_q_b  = (const float*)d_in[1];
    const float* x_kv_a = (const float*)d_in[2];
    const float* x_kv_b = (const float*)d_in[3];
    // d_in[4] = mask -- causal, encoded in the attention kernel
    const float* layer_theta = (const float*)d_in[5];
    const float* thetas_head = (const float*)d_in[6];
    const float* q_wa = (const float*)d_in[7];
    const float* q_wb = (const float*)d_in[8];
    const float* q_ba = (const float*)d_in[9];
    const float* q_bb = (const float*)d_in[10];
    const float* k_wa = (const float*)d_in[11];
    const float* k_wb = (const float*)d_in[12];
    const float* k_ba = (const float*)d_in[13];
    const float* k_bb = (const float*)d_in[14];
    const float* v_wa = (const float*)d_in[15];
    const float* v_wb = (const float*)d_in[16];
    const float* v_ba = (const float*)d_in[17];
    const float* v_bb = (const float*)d_in[18];
    const float* o_wa = (const float*)d_in[19];
    const float* o_wb = (const float*)d_in[20];
    const float* o_ba = (const float*)d_in[21];
    const float* o_bb = (const float*)d_in[22];

    float *qa, *qb, *ka, *kb, *va, *vb, *oa, *ob;
    cudaGetSymbolAddress((void**)&qa, g_qa);
    cudaGetSymbolAddress((void**)&qb, g_qb);
    cudaGetSymbolAddress((void**)&ka, g_ka);
    cudaGetSymbolAddress((void**)&kb, g_kb);
    cudaGetSymbolAddress((void**)&va, g_va);
    cudaGetSymbolAddress((void**)&vb, g_vb);
    cudaGetSymbolAddress((void**)&oa, g_oa);
    cudaGetSymbolAddress((void**)&ob, g_ob);

    __nv_bfloat16 *wH, *wL, *xH, *xL;
    cudaGetSymbolAddress((void**)&wH, g_wH);
    cudaGetSymbolAddress((void**)&wL, g_wL);
    cudaGetSymbolAddress((void**)&xH, g_xH);
    cudaGetSymbolAddress((void**)&xL, g_xL);
    const size_t WSZ = (size_t)EG * EG;
    const size_t XSZ = (size_t)MG * EG;
    auto whi = [&](int i) { return wH + i * WSZ; };
    auto wlo = [&](int i) { return wL + i * WSZ; };
    auto xhi = [&](int i) { return xH + i * XSZ; };
    auto xlo = [&](int i) { return xL + i * XSZ; };

    float* outA = (float*)d_out;
    float* outB = (float*)d_out + (size_t)MG * EG;

    const int GSMEM = 2 * 8 * TILE_HF * (int)sizeof(__nv_bfloat16);  // 81920
    cudaFuncSetAttribute(qc_gemm_bf16_kernel,
                         cudaFuncAttributeMaxDynamicSharedMemorySize, GSMEM);

    // ---- split weights (8 matrices) ----
    {
        SplitBatch sb = {};
        const float* srcs[8] = { q_wa, q_wb, k_wa, k_wb, v_wa, v_wb, o_wa, o_wb };
        for (int i = 0; i < 8; i++) { sb.src[i] = srcs[i]; sb.hi[i] = whi(i); sb.lo[i] = wlo(i); }
        split_kernel<<<dim3((WSZ / 4 + 255) / 256, 8), 256>>>(sb, (int)(WSZ / 4));
    }
    // ---- split input activations (4 tensors) ----
    {
        SplitBatch sb = {};
        const float* srcs[4] = { x_q_a, x_q_b, x_kv_a, x_kv_b };
        for (int i = 0; i < 4; i++) { sb.src[i] = srcs[i]; sb.hi[i] = xhi(i); sb.lo[i] = xlo(i); }
        split_kernel<<<dim3((XSZ / 4 + 255) / 256, 4), 256>>>(sb, (int)(XSZ / 4));
    }

    const dim3 gg(EG / 64, MG / 64);

    // q / k / v projections
    qc_gemm_bf16_kernel<<<gg, 256, GSMEM>>>(
        xhi(0), xlo(0), xhi(1), xlo(1), whi(0), wlo(0), whi(1), wlo(1),
        q_ba, q_bb, layer_theta, qa, qb);
    qc_gemm_bf16_kernel<<<gg, 256, GSMEM>>>(
        xhi(2), xlo(2), xhi(3), xlo(3), whi(2), wlo(2), whi(3), wlo(3),
        k_ba, k_bb, layer_theta, ka, kb);
    qc_gemm_bf16_kernel<<<gg, 256, GSMEM>>>(
        xhi(2), xlo(2), xhi(3), xlo(3), whi(4), wlo(4), whi(5), wlo(5),
        v_ba, v_bb, layer_theta, va, vb);

    // RoPE on qa,qb,ka,kb (in place)
    rope_kernel<<<(4 * MG * (EG / 2)) / 256, 256>>>();

    // tensor-core flash complex-magnitude attention -> g_oa, g_ob
    attn_mma_kernel<<<dim3(SG / 128, HG, 2), 256>>>(thetas_head);

    // ---- split attention outputs (2 tensors) ----
    {
        SplitBatch sb = {};
        sb.src[0] = oa; sb.hi[0] = xhi(4); sb.lo[0] = xlo(4);
        sb.src[1] = ob; sb.hi[1] = xhi(5); sb.lo[1] = xlo(5);
        split_kernel<<<dim3((XSZ / 4 + 255) / 256, 2), 256>>>(sb, (int)(XSZ / 4));
    }

    // output projection straight into d_out (out_a then out_b)
    qc_gemm_bf16_kernel<<<gg, 256, GSMEM>>>(
        xhi(4), xlo(4), xhi(5), xlo(5), whi(6), wlo(6), whi(7), wlo(7),
        o_ba, o_bb, layer_theta, outA, outB);
}